// round 7
// baseline (speedup 1.0000x reference)
#include <cuda_runtime.h>
#include <math.h>
#include <stdint.h>

#define BB 256     // batch
#define TT 512     // time steps
#define DIN 128    // input dim
#define HH 256     // hidden
#define G4 1024    // 4*H
#define OUTF 128   // final out features
#define BHH (BB * HH)

#define NB_CTAS 128
#define NGROUPS 8        // batch-tile groups (32 rows each)
#define GROUP_CTAS 16
#define WPAD 260
#define GW_FLOATS (64 * WPAD + 32 * WPAD)   // W tile + h tile

typedef unsigned long long ull;

// ---------------- scratch (device globals; no allocations allowed) ----------
__device__ float g_XP[(size_t)TT * BB * G4];    // x_proj [T,B,4H]
__device__ float g_HSEQ[(size_t)TT * BB * HH];  // layer-0 h sequence [T,B,H]
__device__ float g_HLAST[BHH];                  // final h of a layer
__device__ float g_h[2][BHH];                   // ping-pong hidden state
__device__ unsigned g_count[NGROUPS];           // per-group barrier counters

// ---------------- helpers ----------------------------------------------------
__device__ __forceinline__ void ffma2(ull& d, ull a, ull b) {
    asm("fma.rn.f32x2 %0, %1, %2, %0;" : "+l"(d) : "l"(a), "l"(b));
}
__device__ __forceinline__ float red2(ull v) {
    float lo = __uint_as_float((unsigned)(v & 0xffffffffu));
    float hi = __uint_as_float((unsigned)(v >> 32));
    return lo + hi;
}
__device__ __forceinline__ float fsig(float x) {
    return __fdividef(1.f, 1.f + __expf(-x));
}
__device__ __forceinline__ float ftanh(float x) {
    return 2.f * __fdividef(1.f, 1.f + __expf(-2.f * x)) - 1.f;
}
__device__ __forceinline__ unsigned ld_acq(const unsigned* p) {
    unsigned v;
    asm volatile("ld.acquire.gpu.global.u32 %0, [%1];" : "=r"(v) : "l"(p) : "memory");
    return v;
}
__device__ __forceinline__ void red_rel_add1(unsigned* p) {
    asm volatile("red.release.gpu.global.add.u32 [%0], 1;" :: "l"(p) : "memory");
}

// ---------------- init: zero h[0] and barrier counters ------------------------
__global__ void init_kernel() {
    int i = blockIdx.x * blockDim.x + threadIdx.x;
    if (i < BHH) g_h[0][i] = 0.f;
    if (i < NGROUPS) g_count[i] = 0u;
}

// ---------------- generic GEMM + bias (f32x2) -- validated R3 -----------------
template <int K>
__global__ void gemm_bias_kernel(const float* __restrict__ A,
                                 size_t rowStrideB, size_t strideT,
                                 const float* __restrict__ W,
                                 const float* __restrict__ b1,
                                 const float* __restrict__ b2,
                                 float* __restrict__ outp, int ldOut)
{
    __shared__ __align__(16) float As[64][68];
    __shared__ __align__(16) float Ws[64][68];

    const int t   = blockIdx.z;
    const int bb  = blockIdx.y * 64;
    const int nn  = blockIdx.x * 64;
    const int tid = threadIdx.x;
    const int r0  = tid & 15;
    const int c0  = tid >> 4;

    ull acc2[4][4];
#pragma unroll
    for (int m = 0; m < 4; m++)
#pragma unroll
        for (int n = 0; n < 4; n++) acc2[m][n] = 0ull;

    const float* Abase = A + (size_t)bb * rowStrideB + (size_t)t * strideT;
    const float* Wbase = W + (size_t)nn * K;

    for (int kt = 0; kt < K; kt += 64) {
#pragma unroll
        for (int i = 0; i < 4; i++) {
            int lin = i * 256 + tid;
            int row = lin >> 4;
            int c4  = (lin & 15) * 4;
            *(float4*)&As[row][c4] =
                *(const float4*)(Abase + (size_t)row * rowStrideB + kt + c4);
            *(float4*)&Ws[row][c4] =
                *(const float4*)(Wbase + (size_t)row * K + kt + c4);
        }
        __syncthreads();

#pragma unroll
        for (int k = 0; k < 64; k += 4) {
            ulonglong2 a2[4], w2[4];
#pragma unroll
            for (int m = 0; m < 4; m++) a2[m] = *(ulonglong2*)&As[r0 + 16 * m][k];
#pragma unroll
            for (int n = 0; n < 4; n++) w2[n] = *(ulonglong2*)&Ws[c0 + 16 * n][k];
#pragma unroll
            for (int m = 0; m < 4; m++)
#pragma unroll
                for (int n = 0; n < 4; n++) {
                    ffma2(acc2[m][n], a2[m].x, w2[n].x);
                    ffma2(acc2[m][n], a2[m].y, w2[n].y);
                }
        }
        __syncthreads();
    }

#pragma unroll
    for (int m = 0; m < 4; m++)
#pragma unroll
        for (int n = 0; n < 4; n++) {
            int row = bb + r0 + 16 * m;
            int col = nn + c0 + 16 * n;
            float bias = (b1 != nullptr) ? (b1[col] + b2[col]) : 0.f;
            outp[((size_t)t * BB + row) * ldOut + col] = red2(acc2[m][n]) + bias;
        }
}

// ---------------- persistent LSTM layer (group barrier, 256 threads) ----------
// 128 CTAs x 256 threads. CTA (jt,bt): hidden slice jj..jj+15, batch bb..bb+31.
// W_hh slice in SMEM, c in registers, h via global ping-pong through L2.
// Barrier: red.release arrive / ld.acquire poll among 16 CTAs of group bt.
// Thread (jl=tid>>4, br=tid&15): batch rows br, br+16; hidden jj+jl; 4 gates.
__global__ void __launch_bounds__(256, 1)
lstm_group_kernel(const float* __restrict__ xp,    // [T,B,4H]
                  const float* __restrict__ Whh,   // [4H,H]
                  float* __restrict__ hbuf,        // [2][B,H]
                  float* __restrict__ hseq,        // [T,B,H] or null
                  float* __restrict__ hlast)       // [B,H]
{
    extern __shared__ __align__(16) float smg[];
    float* Ws = smg;              // [64][WPAD]
    float* Hs = smg + 64 * WPAD;  // [32][WPAD]

    const int tid = threadIdx.x;
    const int jt  = blockIdx.x & 15;
    const int bt  = blockIdx.x >> 4;
    const int jj  = jt * 16;
    const int bb  = bt * 32;
    const int jl  = tid >> 4;     // 0..15 hidden unit within tile
    const int br  = tid & 15;     // batch rows br, br+16
    const int j   = jj + jl;
    unsigned* cnt = &g_count[bt];

    // ---- load W_hh slice once: smem row = g*16 + jloc
#pragma unroll
    for (int i = 0; i < 16; i++) {
        int lin  = i * 256 + tid;       // 0..4095 float4 units
        int srow = lin >> 6;            // 0..63
        int c4   = (lin & 63) * 4;
        int g    = srow >> 4;
        int jloc = srow & 15;
        *(float4*)&Ws[srow * WPAD + c4] =
            *(const float4*)(Whh + (size_t)(g * HH + jj + jloc) * HH + c4);
    }

    float cacc[2] = {0.f, 0.f};

    // ---- prefetch x_proj for step 0
    float xv_cur[2][4], xv_nxt[2][4];
#pragma unroll
    for (int m = 0; m < 2; m++) {
        const float* xr = xp + (size_t)(bb + br + 16 * m) * G4;
#pragma unroll
        for (int g = 0; g < 4; g++) xv_cur[m][g] = __ldg(xr + g * HH + j);
    }
    __syncthreads();   // Ws ready

    for (int t = 0; t < TT; t++) {
        // ---- wait for h(t) (all group CTAs arrived t times)
        if (t > 0) {
            if (tid == 0) {
                unsigned target = (unsigned)t * GROUP_CTAS;
                while (ld_acq(cnt) < target) {}
            }
            __syncthreads();
        }

        // ---- stage h tile (32 x 256) into SMEM
        const float* hin = hbuf + (size_t)(t & 1) * BHH;
#pragma unroll
        for (int i = 0; i < 8; i++) {
            int lin = i * 256 + tid;    // 0..2047 float4 units
            int row = lin >> 6;         // 0..31
            int c4  = (lin & 63) * 4;
            float4 v = __ldcg((const float4*)(hin + (size_t)(bb + row) * HH + c4));
            *(float4*)&Hs[row * WPAD + c4] = v;
        }
        __syncthreads();

        // ---- kick off next step's x_proj loads (h-independent)
        if (t + 1 < TT) {
            const float* xpt = xp + (size_t)(t + 1) * BB * G4;
#pragma unroll
            for (int m = 0; m < 2; m++) {
                const float* xr = xpt + (size_t)(bb + br + 16 * m) * G4;
#pragma unroll
                for (int g = 0; g < 4; g++) xv_nxt[m][g] = __ldg(xr + g * HH + j);
            }
        }

        // ---- GEMM: acc[m][g] = h[b_m,:] . Whh[g*256+j,:]   (f32x2 packed k)
        ull acc2[2][4];
#pragma unroll
        for (int m = 0; m < 2; m++)
#pragma unroll
            for (int g = 0; g < 4; g++) acc2[m][g] = 0ull;

#pragma unroll 4
        for (int k = 0; k < HH; k += 4) {
            ulonglong2 h2[2], w2[4];
#pragma unroll
            for (int m = 0; m < 2; m++)
                h2[m] = *(ulonglong2*)&Hs[(br + 16 * m) * WPAD + k];
#pragma unroll
            for (int g = 0; g < 4; g++)
                w2[g] = *(ulonglong2*)&Ws[(g * 16 + jl) * WPAD + k];
#pragma unroll
            for (int m = 0; m < 2; m++)
#pragma unroll
                for (int g = 0; g < 4; g++) {
                    ffma2(acc2[m][g], h2[m].x, w2[g].x);
                    ffma2(acc2[m][g], h2[m].y, w2[g].y);
                }
        }

        // ---- gates + state update; write h(t+1)
        float* hout = hbuf + (size_t)((t + 1) & 1) * BHH;
#pragma unroll
        for (int m = 0; m < 2; m++) {
            int b = bb + br + 16 * m;
            float vi = red2(acc2[m][0]) + xv_cur[m][0];
            float vf = red2(acc2[m][1]) + xv_cur[m][1];
            float vg = red2(acc2[m][2]) + xv_cur[m][2];
            float vo = red2(acc2[m][3]) + xv_cur[m][3];

            float ig = fsig(vi);
            float fg = fsig(vf);
            float gg = ftanh(vg);
            float og = fsig(vo);

            float cn = fg * cacc[m] + ig * gg;
            cacc[m] = cn;
            float hn = og * ftanh(cn);
            __stcg(hout + (size_t)b * HH + j, hn);
            if (hseq != nullptr) hseq[(size_t)t * BHH + (size_t)b * HH + j] = hn;
            if (t == TT - 1) hlast[(size_t)b * HH + j] = hn;
        }

        // ---- release-arrive (stores above ordered by bar + release)
        __syncthreads();
        if (tid == 0) red_rel_add1(cnt);

#pragma unroll
        for (int m = 0; m < 2; m++)
#pragma unroll
            for (int g = 0; g < 4; g++) xv_cur[m][g] = xv_nxt[m][g];
    }
}

// ---------------- launcher ---------------------------------------------------
extern "C" void kernel_launch(void* const* d_in, const int* in_sizes, int n_in,
                              void* d_out, int out_size)
{
    const float* x     = (const float*)d_in[0];
    const float* W_ih0 = (const float*)d_in[1];
    const float* W_hh0 = (const float*)d_in[2];
    const float* b_ih0 = (const float*)d_in[3];
    const float* b_hh0 = (const float*)d_in[4];
    const float* W_ih1 = (const float*)d_in[5];
    const float* W_hh1 = (const float*)d_in[6];
    const float* b_ih1 = (const float*)d_in[7];
    const float* b_hh1 = (const float*)d_in[8];
    const float* W_fc  = (const float*)d_in[9];
    float* outp = (float*)d_out;
    (void)in_sizes; (void)n_in; (void)out_size;

    float *XP, *HSEQ, *HLAST, *Hbuf;
    cudaGetSymbolAddress((void**)&XP,    g_XP);
    cudaGetSymbolAddress((void**)&HSEQ,  g_HSEQ);
    cudaGetSymbolAddress((void**)&HLAST, g_HLAST);
    cudaGetSymbolAddress((void**)&Hbuf,  g_h);

    static bool attr_set = false;
    if (!attr_set) {
        cudaFuncSetAttribute(lstm_group_kernel,
                             cudaFuncAttributeMaxDynamicSharedMemorySize,
                             GW_FLOATS * (int)sizeof(float));
        attr_set = true;
    }
    const size_t gsmemB = GW_FLOATS * sizeof(float);

    // ---------- layer 0 ----------
    init_kernel<<<(BHH + 255) / 256, 256>>>();
    gemm_bias_kernel<DIN><<<dim3(16, 4, TT), 256>>>(
        x, (size_t)TT * DIN, (size_t)DIN, W_ih0, b_ih0, b_hh0, XP, G4);
    lstm_group_kernel<<<NB_CTAS, 256, gsmemB>>>(XP, W_hh0, Hbuf, HSEQ, HLAST);

    // ---------- layer 1 ----------
    init_kernel<<<(BHH + 255) / 256, 256>>>();
    gemm_bias_kernel<HH><<<dim3(16, 4, TT), 256>>>(
        HSEQ, (size_t)HH, (size_t)BB * HH, W_ih1, b_ih1, b_hh1, XP, G4);
    lstm_group_kernel<<<NB_CTAS, 256, gsmemB>>>(XP, W_hh1, Hbuf, nullptr, HLAST);

    // ---------- final FC: out = h_last @ W_fc^T ----------
    gemm_bias_kernel<HH><<<dim3(2, 4, 1), 256>>>(
        HLAST, (size_t)HH, 0, W_fc, nullptr, nullptr, outp, OUTF);
}

// round 8
// speedup vs baseline: 1.6968x; 1.6968x over previous
#include <cuda_runtime.h>
#include <math.h>
#include <stdint.h>

#define BB 256     // batch
#define TT 512     // time steps
#define DIN 128    // input dim
#define HH 256     // hidden
#define G4 1024    // 4*H
#define OUTF 128   // final out features
#define BHH (BB * HH)

#define NB_CTAS 128
#define NGROUPS 8        // batch-tile groups (32 rows each)
#define GROUP_CTAS 16
#define WPAD 260
#define RPAD 68
#define RS_FLOATS (32 * RPAD)                        // partial-sum buffer
#define GW_FLOATS (64 * WPAD + 32 * WPAD + RS_FLOATS)

typedef unsigned long long ull;

// ---------------- scratch (device globals; no allocations allowed) ----------
__device__ float g_XP[(size_t)TT * BB * G4];    // x_proj [T,B,4H]
__device__ float g_HSEQ[(size_t)TT * BB * HH];  // layer-0 h sequence [T,B,H]
__device__ float g_HLAST[BHH];                  // final h of a layer
__device__ float g_h[2][BHH];                   // ping-pong hidden state
__device__ unsigned g_flag[NGROUPS * GROUP_CTAS * 32];  // per-CTA flags, 128B apart

// ---------------- helpers ----------------------------------------------------
__device__ __forceinline__ void ffma2(ull& d, ull a, ull b) {
    asm("fma.rn.f32x2 %0, %1, %2, %0;" : "+l"(d) : "l"(a), "l"(b));
}
__device__ __forceinline__ float red2(ull v) {
    float lo = __uint_as_float((unsigned)(v & 0xffffffffu));
    float hi = __uint_as_float((unsigned)(v >> 32));
    return lo + hi;
}
__device__ __forceinline__ float fsig(float x) {
    return __fdividef(1.f, 1.f + __expf(-x));
}
__device__ __forceinline__ float ftanh(float x) {
    return 2.f * __fdividef(1.f, 1.f + __expf(-2.f * x)) - 1.f;
}

// ---------------- init: zero h[0] and flags -----------------------------------
__global__ void init_kernel() {
    int i = blockIdx.x * blockDim.x + threadIdx.x;
    if (i < BHH) g_h[0][i] = 0.f;
    if (i < NGROUPS * GROUP_CTAS * 32) g_flag[i] = 0u;
}

// ---------------- generic GEMM + bias (f32x2) -- validated R3 -----------------
template <int K>
__global__ void gemm_bias_kernel(const float* __restrict__ A,
                                 size_t rowStrideB, size_t strideT,
                                 const float* __restrict__ W,
                                 const float* __restrict__ b1,
                                 const float* __restrict__ b2,
                                 float* __restrict__ outp, int ldOut)
{
    __shared__ __align__(16) float As[64][68];
    __shared__ __align__(16) float Ws[64][68];

    const int t   = blockIdx.z;
    const int bb  = blockIdx.y * 64;
    const int nn  = blockIdx.x * 64;
    const int tid = threadIdx.x;
    const int r0  = tid & 15;
    const int c0  = tid >> 4;

    ull acc2[4][4];
#pragma unroll
    for (int m = 0; m < 4; m++)
#pragma unroll
        for (int n = 0; n < 4; n++) acc2[m][n] = 0ull;

    const float* Abase = A + (size_t)bb * rowStrideB + (size_t)t * strideT;
    const float* Wbase = W + (size_t)nn * K;

    for (int kt = 0; kt < K; kt += 64) {
#pragma unroll
        for (int i = 0; i < 4; i++) {
            int lin = i * 256 + tid;
            int row = lin >> 4;
            int c4  = (lin & 15) * 4;
            *(float4*)&As[row][c4] =
                *(const float4*)(Abase + (size_t)row * rowStrideB + kt + c4);
            *(float4*)&Ws[row][c4] =
                *(const float4*)(Wbase + (size_t)row * K + kt + c4);
        }
        __syncthreads();

#pragma unroll
        for (int k = 0; k < 64; k += 4) {
            ulonglong2 a2[4], w2[4];
#pragma unroll
            for (int m = 0; m < 4; m++) a2[m] = *(ulonglong2*)&As[r0 + 16 * m][k];
#pragma unroll
            for (int n = 0; n < 4; n++) w2[n] = *(ulonglong2*)&Ws[c0 + 16 * n][k];
#pragma unroll
            for (int m = 0; m < 4; m++)
#pragma unroll
                for (int n = 0; n < 4; n++) {
                    ffma2(acc2[m][n], a2[m].x, w2[n].x);
                    ffma2(acc2[m][n], a2[m].y, w2[n].y);
                }
        }
        __syncthreads();
    }

#pragma unroll
    for (int m = 0; m < 4; m++)
#pragma unroll
        for (int n = 0; n < 4; n++) {
            int row = bb + r0 + 16 * m;
            int col = nn + c0 + 16 * n;
            float bias = (b1 != nullptr) ? (b1[col] + b2[col]) : 0.f;
            outp[((size_t)t * BB + row) * ldOut + col] = red2(acc2[m][n]) + bias;
        }
}

// ---------------- persistent LSTM layer (k-split, 256 threads) -----------------
// 128 CTAs x 256 threads. CTA (jt,bt): hidden slice jj..jj+15, batch bb..bb+31.
// Two warpgroups kg=0,1 each compute the SAME 4x4 tile (R3 mapping:
// jl=lt>>3, br=lt&7, rows br+8m) over half the k range; kg=1 partials go
// through SMEM Rs; kg=0 adds them and runs the gate epilogue.
__global__ void __launch_bounds__(256, 1)
lstm_group_kernel(const float* __restrict__ xp,    // [T,B,4H]
                  const float* __restrict__ Whh,   // [4H,H]
                  float* __restrict__ hbuf,        // [2][B,H]
                  float* __restrict__ hseq,        // [T,B,H] or null
                  float* __restrict__ hlast)       // [B,H]
{
    extern __shared__ __align__(16) float smg[];
    float* Ws = smg;                         // [64][WPAD]
    float* Hs = smg + 64 * WPAD;             // [32][WPAD]
    float* Rs = smg + 96 * WPAD;             // [32][RPAD] partials

    const int tid = threadIdx.x;
    const int jt  = blockIdx.x & 15;
    const int bt  = blockIdx.x >> 4;
    const int jj  = jt * 16;
    const int bb  = bt * 32;
    const int kg  = tid >> 7;       // warpgroup: k half
    const int lt  = tid & 127;
    const int jl  = lt >> 3;        // 0..15 hidden unit within tile
    const int br  = lt & 7;         // batch rows br,br+8,br+16,br+24
    const int j   = jj + jl;
    const int kb  = kg * 128;       // k base for this warpgroup

    // ---- load W_hh slice once: smem row = g*16 + jloc
#pragma unroll
    for (int i = 0; i < 16; i++) {
        int lin  = i * 256 + tid;       // 0..4095 float4 units
        int srow = lin >> 6;            // 0..63
        int c4   = (lin & 63) * 4;
        int g    = srow >> 4;
        int jloc = srow & 15;
        *(float4*)&Ws[srow * WPAD + c4] =
            *(const float4*)(Whh + (size_t)(g * HH + jj + jloc) * HH + c4);
    }

    float cacc[4] = {0.f, 0.f, 0.f, 0.f};
    float xv_cur[4][4], xv_nxt[4][4];
    if (kg == 0) {
#pragma unroll
        for (int m = 0; m < 4; m++) {
            const float* xr = xp + (size_t)(bb + br + 8 * m) * G4;
#pragma unroll
            for (int g = 0; g < 4; g++) xv_cur[m][g] = __ldg(xr + g * HH + j);
        }
    }
    __syncthreads();   // Ws ready

    for (int t = 0; t < TT; t++) {
        // ---- wait for all group CTAs to have finished step t-1
        if (t > 0) {
            if (tid < GROUP_CTAS) {
                volatile unsigned* f = &g_flag[(bt * GROUP_CTAS + tid) * 32];
                while (*f < (unsigned)t) {}
                __threadfence();
            }
            __syncthreads();
        }

        // ---- stage h tile (32 x 256) into SMEM
        const float* hin = hbuf + (size_t)(t & 1) * BHH;
#pragma unroll
        for (int i = 0; i < 8; i++) {
            int lin = i * 256 + tid;    // 0..2047 float4 units
            int row = lin >> 6;         // 0..31
            int c4  = (lin & 63) * 4;
            float4 v = __ldcg((const float4*)(hin + (size_t)(bb + row) * HH + c4));
            *(float4*)&Hs[row * WPAD + c4] = v;
        }
        __syncthreads();

        // ---- prefetch next step's x_proj (h-independent, hides DRAM latency)
        if (kg == 0 && t + 1 < TT) {
            const float* xpt = xp + (size_t)(t + 1) * BB * G4;
#pragma unroll
            for (int m = 0; m < 4; m++) {
                const float* xr = xpt + (size_t)(bb + br + 8 * m) * G4;
#pragma unroll
                for (int g = 0; g < 4; g++) xv_nxt[m][g] = __ldg(xr + g * HH + j);
            }
        }

        // ---- half-K GEMM: acc[m][g] = sum_{k in half} h[b_m,k]*Whh[g*256+j,k]
        ull acc2[4][4];
#pragma unroll
        for (int m = 0; m < 4; m++)
#pragma unroll
            for (int g = 0; g < 4; g++) acc2[m][g] = 0ull;

#pragma unroll 4
        for (int k = kb; k < kb + 128; k += 4) {
            ulonglong2 h2[4], w2[4];
#pragma unroll
            for (int m = 0; m < 4; m++)
                h2[m] = *(ulonglong2*)&Hs[(br + 8 * m) * WPAD + k];
#pragma unroll
            for (int g = 0; g < 4; g++)
                w2[g] = *(ulonglong2*)&Ws[(g * 16 + jl) * WPAD + k];
#pragma unroll
            for (int m = 0; m < 4; m++)
#pragma unroll
                for (int g = 0; g < 4; g++) {
                    ffma2(acc2[m][g], h2[m].x, w2[g].x);
                    ffma2(acc2[m][g], h2[m].y, w2[g].y);
                }
        }

        // ---- kg=1 publishes partials (conflict-free: bank = 4*br+jl)
        if (kg == 1) {
#pragma unroll
            for (int m = 0; m < 4; m++)
#pragma unroll
                for (int g = 0; g < 4; g++)
                    Rs[(8 * m + br) * RPAD + g * 16 + jl] = red2(acc2[m][g]);
        }
        __syncthreads();

        // ---- kg=0: combine, gates, state update, write h(t+1)
        if (kg == 0) {
            float* hout = hbuf + (size_t)((t + 1) & 1) * BHH;
#pragma unroll
            for (int m = 0; m < 4; m++) {
                int b = bb + br + 8 * m;
                const float* rrow = &Rs[(8 * m + br) * RPAD];
                float vi = red2(acc2[m][0]) + rrow[0 * 16 + jl] + xv_cur[m][0];
                float vf = red2(acc2[m][1]) + rrow[1 * 16 + jl] + xv_cur[m][1];
                float vg = red2(acc2[m][2]) + rrow[2 * 16 + jl] + xv_cur[m][2];
                float vo = red2(acc2[m][3]) + rrow[3 * 16 + jl] + xv_cur[m][3];

                float ig = fsig(vi);
                float fg = fsig(vf);
                float gg = ftanh(vg);
                float og = fsig(vo);

                float cn = fg * cacc[m] + ig * gg;
                cacc[m] = cn;
                float hn = og * ftanh(cn);
                __stcg(hout + (size_t)b * HH + j, hn);
                if (hseq != nullptr) hseq[(size_t)t * BHH + (size_t)b * HH + j] = hn;
                if (t == TT - 1) hlast[(size_t)b * HH + j] = hn;

#pragma unroll
                for (int g = 0; g < 4; g++) xv_cur[m][g] = xv_nxt[m][g];
            }
        }

        // ---- arrive: all h stores issued, then flag = t+1
        __syncthreads();
        if (tid == 0) {
            __threadfence();
            *(volatile unsigned*)&g_flag[(bt * GROUP_CTAS + jt) * 32] =
                (unsigned)(t + 1);
        }
    }
}

// ---------------- launcher ---------------------------------------------------
extern "C" void kernel_launch(void* const* d_in, const int* in_sizes, int n_in,
                              void* d_out, int out_size)
{
    const float* x     = (const float*)d_in[0];
    const float* W_ih0 = (const float*)d_in[1];
    const float* W_hh0 = (const float*)d_in[2];
    const float* b_ih0 = (const float*)d_in[3];
    const float* b_hh0 = (const float*)d_in[4];
    const float* W_ih1 = (const float*)d_in[5];
    const float* W_hh1 = (const float*)d_in[6];
    const float* b_ih1 = (const float*)d_in[7];
    const float* b_hh1 = (const float*)d_in[8];
    const float* W_fc  = (const float*)d_in[9];
    float* outp = (float*)d_out;
    (void)in_sizes; (void)n_in; (void)out_size;

    float *XP, *HSEQ, *HLAST, *Hbuf;
    cudaGetSymbolAddress((void**)&XP,    g_XP);
    cudaGetSymbolAddress((void**)&HSEQ,  g_HSEQ);
    cudaGetSymbolAddress((void**)&HLAST, g_HLAST);
    cudaGetSymbolAddress((void**)&Hbuf,  g_h);

    static bool attr_set = false;
    if (!attr_set) {
        cudaFuncSetAttribute(lstm_group_kernel,
                             cudaFuncAttributeMaxDynamicSharedMemorySize,
                             GW_FLOATS * (int)sizeof(float));
        attr_set = true;
    }
    const size_t gsmemB = GW_FLOATS * sizeof(float);

    // ---------- layer 0 ----------
    init_kernel<<<(BHH + 255) / 256, 256>>>();
    gemm_bias_kernel<DIN><<<dim3(16, 4, TT), 256>>>(
        x, (size_t)TT * DIN, (size_t)DIN, W_ih0, b_ih0, b_hh0, XP, G4);
    lstm_group_kernel<<<NB_CTAS, 256, gsmemB>>>(XP, W_hh0, Hbuf, HSEQ, HLAST);

    // ---------- layer 1 ----------
    init_kernel<<<(BHH + 255) / 256, 256>>>();
    gemm_bias_kernel<HH><<<dim3(16, 4, TT), 256>>>(
        HSEQ, (size_t)HH, (size_t)BB * HH, W_ih1, b_ih1, b_hh1, XP, G4);
    lstm_group_kernel<<<NB_CTAS, 256, gsmemB>>>(XP, W_hh1, Hbuf, nullptr, HLAST);

    // ---------- final FC: out = h_last @ W_fc^T ----------
    gemm_bias_kernel<HH><<<dim3(2, 4, 1), 256>>>(
        HLAST, (size_t)HH, 0, W_fc, nullptr, nullptr, outp, OUTF);
}

// round 9
// speedup vs baseline: 1.8873x; 1.1123x over previous
#include <cuda_runtime.h>
#include <math.h>
#include <stdint.h>

#define BB 256     // batch
#define TT 512     // time steps
#define DIN 128    // input dim
#define HH 256     // hidden
#define G4 1024    // 4*H
#define OUTF 128   // final out features
#define BHH (BB * HH)

#define NB_CTAS 128
#define NGROUPS 8        // batch-tile groups (32 rows each)
#define GROUP_CTAS 16
#define WPAD 260
#define RPAD 68
#define CPAD 20          // chunk buffer row stride (16 k + 4 pad)

// SMEM layout (floats)
#define OFF_WS0 0
#define OFF_WS1 (64 * WPAD)
#define OFF_HS0 (128 * WPAD)
#define OFF_HS1 (160 * WPAD)
#define OFF_RS  (192 * WPAD)
#define OFF_CB  (OFF_RS + 32 * RPAD)
#define FUSED_FLOATS (OFF_CB + 2 * 2 * 64 * CPAD)   // 57,216 floats = 228,864 B

typedef unsigned long long ull;

// ---------------- scratch (device globals; no allocations allowed) ----------
__device__ float g_XP[(size_t)TT * BB * G4];    // layer-0 x_proj [T,B,4H]
__device__ float g_H0[2 * BHH];                 // layer-0 h ping-pong
__device__ float g_H1[2 * BHH];                 // layer-1 h ping-pong
__device__ float g_HLAST[BHH];                  // final h1
__device__ unsigned g_flag[NGROUPS * GROUP_CTAS * 32];  // per-CTA flags, 128B apart

// ---------------- helpers ----------------------------------------------------
__device__ __forceinline__ void ffma2(ull& d, ull a, ull b) {
    asm("fma.rn.f32x2 %0, %1, %2, %0;" : "+l"(d) : "l"(a), "l"(b));
}
__device__ __forceinline__ float red2(ull v) {
    float lo = __uint_as_float((unsigned)(v & 0xffffffffu));
    float hi = __uint_as_float((unsigned)(v >> 32));
    return lo + hi;
}
__device__ __forceinline__ float fsig(float x) {
    return __fdividef(1.f, 1.f + __expf(-x));
}
__device__ __forceinline__ float ftanh(float x) {
    return 2.f * __fdividef(1.f, 1.f + __expf(-2.f * x)) - 1.f;
}
__device__ __forceinline__ void cp_async16(uint32_t dst, const void* src) {
    asm volatile("cp.async.ca.shared.global [%0], [%1], 16;" :: "r"(dst), "l"(src));
}

// ---------------- init: zero h buffers and flags ------------------------------
__global__ void init_kernel() {
    int i = blockIdx.x * blockDim.x + threadIdx.x;
    if (i < 2 * BHH) { g_H0[i] = 0.f; g_H1[i] = 0.f; }
    if (i < NGROUPS * GROUP_CTAS * 32) g_flag[i] = 0u;
}

// ---------------- generic GEMM + bias (f32x2) -- validated ---------------------
template <int K>
__global__ void gemm_bias_kernel(const float* __restrict__ A,
                                 size_t rowStrideB, size_t strideT,
                                 const float* __restrict__ W,
                                 const float* __restrict__ b1,
                                 const float* __restrict__ b2,
                                 float* __restrict__ outp, int ldOut)
{
    __shared__ __align__(16) float As[64][68];
    __shared__ __align__(16) float Ws[64][68];

    const int t   = blockIdx.z;
    const int bb  = blockIdx.y * 64;
    const int nn  = blockIdx.x * 64;
    const int tid = threadIdx.x;
    const int r0  = tid & 15;
    const int c0  = tid >> 4;

    ull acc2[4][4];
#pragma unroll
    for (int m = 0; m < 4; m++)
#pragma unroll
        for (int n = 0; n < 4; n++) acc2[m][n] = 0ull;

    const float* Abase = A + (size_t)bb * rowStrideB + (size_t)t * strideT;
    const float* Wbase = W + (size_t)nn * K;

    for (int kt = 0; kt < K; kt += 64) {
#pragma unroll
        for (int i = 0; i < 4; i++) {
            int lin = i * 256 + tid;
            int row = lin >> 4;
            int c4  = (lin & 15) * 4;
            *(float4*)&As[row][c4] =
                *(const float4*)(Abase + (size_t)row * rowStrideB + kt + c4);
            *(float4*)&Ws[row][c4] =
                *(const float4*)(Wbase + (size_t)row * K + kt + c4);
        }
        __syncthreads();

#pragma unroll
        for (int k = 0; k < 64; k += 4) {
            ulonglong2 a2[4], w2[4];
#pragma unroll
            for (int m = 0; m < 4; m++) a2[m] = *(ulonglong2*)&As[r0 + 16 * m][k];
#pragma unroll
            for (int n = 0; n < 4; n++) w2[n] = *(ulonglong2*)&Ws[c0 + 16 * n][k];
#pragma unroll
            for (int m = 0; m < 4; m++)
#pragma unroll
                for (int n = 0; n < 4; n++) {
                    ffma2(acc2[m][n], a2[m].x, w2[n].x);
                    ffma2(acc2[m][n], a2[m].y, w2[n].y);
                }
        }
        __syncthreads();
    }

#pragma unroll
    for (int m = 0; m < 4; m++)
#pragma unroll
        for (int n = 0; n < 4; n++) {
            int row = bb + r0 + 16 * m;
            int col = nn + c0 + 16 * n;
            float bias = (b1 != nullptr) ? (b1[col] + b2[col]) : 0.f;
            outp[((size_t)t * BB + row) * ldOut + col] = red2(acc2[m][n]) + bias;
        }
}

// ---------------- fused 2-layer persistent LSTM --------------------------------
// 128 CTAs x 256 threads. CTA (jt,bt): hidden slice jj..jj+15, batch bb..bb+31,
// for BOTH layers. Iteration u (0..TT): layer0 computes h0(u) (skip u==TT);
// layer1 computes h1(u-1) = f(h1(u-2), h0(u-1)) with W_ih1 folded in-step
// (skip u==0). One group barrier per iteration. K-split across 2 warpgroups.
__global__ void __launch_bounds__(256, 1)
lstm_fused_kernel(const float* __restrict__ xp,     // [T,B,4H] layer-0 x_proj
                  const float* __restrict__ Whh0,   // [4H,H]
                  const float* __restrict__ Whh1,   // [4H,H]
                  const float* __restrict__ Wih1,   // [4H,H]
                  const float* __restrict__ bih1,
                  const float* __restrict__ bhh1,
                  float* __restrict__ h0buf,        // [2][B,H]
                  float* __restrict__ h1buf,        // [2][B,H]
                  float* __restrict__ hlast)        // [B,H]
{
    extern __shared__ __align__(16) float smg[];
    float* Ws0 = smg + OFF_WS0;   // [64][WPAD]
    float* Ws1 = smg + OFF_WS1;   // [64][WPAD]
    float* Hs0 = smg + OFF_HS0;   // [32][WPAD]
    float* Hs1 = smg + OFF_HS1;   // [32][WPAD]
    float* Rs  = smg + OFF_RS;    // [32][RPAD]
    float* Cb  = smg + OFF_CB;    // [2 kg][2 buf][64][CPAD]

    const int tid = threadIdx.x;
    const int jt  = blockIdx.x & 15;
    const int bt  = blockIdx.x >> 4;
    const int jj  = jt * 16;
    const int bb  = bt * 32;
    const int kg  = tid >> 7;        // warpgroup: k half
    const int lt  = tid & 127;
    const int jl  = lt >> 3;         // 0..15 hidden unit within tile
    const int br  = lt & 7;          // batch rows br,br+8,br+16,br+24
    const int j   = jj + jl;
    const int kb  = kg * 128;        // k base for this warpgroup
    uint32_t cb_u32 = (uint32_t)__cvta_generic_to_shared(Cb) +
                      (uint32_t)(kg * 2 * 64 * CPAD * 4);
    float* cb_kg = Cb + kg * 2 * 64 * CPAD;

    // ---- load both W_hh slices: smem row = g*16 + jloc
#pragma unroll
    for (int i = 0; i < 16; i++) {
        int lin  = i * 256 + tid;       // 0..4095 float4 units
        int srow = lin >> 6;            // 0..63
        int c4   = (lin & 63) * 4;
        int g    = srow >> 4;
        int jloc = srow & 15;
        size_t grow = (size_t)(g * HH + jj + jloc) * HH + c4;
        *(float4*)&Ws0[srow * WPAD + c4] = *(const float4*)(Whh0 + grow);
        *(float4*)&Ws1[srow * WPAD + c4] = *(const float4*)(Whh1 + grow);
    }

    float cacc0[4] = {0.f, 0.f, 0.f, 0.f};
    float cacc1[4] = {0.f, 0.f, 0.f, 0.f};
    float bias1[4];
    float xv_cur[4][4], xv_nxt[4][4];
    if (kg == 0) {
#pragma unroll
        for (int g = 0; g < 4; g++)
            bias1[g] = bih1[g * HH + j] + bhh1[g * HH + j];
#pragma unroll
        for (int m = 0; m < 4; m++) {
            const float* xr = xp + (size_t)(bb + br + 8 * m) * G4;
#pragma unroll
            for (int g = 0; g < 4; g++) xv_cur[m][g] = __ldg(xr + g * HH + j);
        }
    }
    __syncthreads();   // W slices ready

    for (int u = 0; u <= TT; u++) {
        // ---- wait for all group CTAs to have finished iteration u-1
        if (u > 0) {
            if (tid < GROUP_CTAS) {
                volatile unsigned* f = &g_flag[(bt * GROUP_CTAS + tid) * 32];
                while (*f < (unsigned)u) {}
                __threadfence();
            }
            __syncthreads();
        }

        // ---- stage h0(u-1) and h1(u-2) tiles into SMEM
        const float* hin0 = h0buf + (size_t)((u + 1) & 1) * BHH;
        const float* hin1 = h1buf + (size_t)(u & 1) * BHH;
#pragma unroll
        for (int i = 0; i < 8; i++) {
            int lin = i * 256 + tid;    // 0..2047 float4 units
            int row = lin >> 6;         // 0..31
            int c4  = (lin & 63) * 4;
            size_t goff = (size_t)(bb + row) * HH + c4;
            *(float4*)&Hs0[row * WPAD + c4] = __ldcg((const float4*)(hin0 + goff));
            *(float4*)&Hs1[row * WPAD + c4] = __ldcg((const float4*)(hin1 + goff));
        }
        __syncthreads();

        // ---- prefetch next iteration's x_proj (layer 0)
        if (kg == 0 && u + 1 < TT) {
            const float* xpt = xp + (size_t)(u + 1) * BB * G4;
#pragma unroll
            for (int m = 0; m < 4; m++) {
                const float* xr = xpt + (size_t)(bb + br + 8 * m) * G4;
#pragma unroll
                for (int g = 0; g < 4; g++) xv_nxt[m][g] = __ldg(xr + g * HH + j);
            }
        }

        // ================= layer 0 GEMM: h0(u-1) . W_hh0 =================
        ull acc0[4][4];
#pragma unroll
        for (int m = 0; m < 4; m++)
#pragma unroll
            for (int g = 0; g < 4; g++) acc0[m][g] = 0ull;

        if (u < TT) {
#pragma unroll 4
            for (int k = kb; k < kb + 128; k += 4) {
                ulonglong2 h2[4], w2[4];
#pragma unroll
                for (int m = 0; m < 4; m++)
                    h2[m] = *(ulonglong2*)&Hs0[(br + 8 * m) * WPAD + k];
#pragma unroll
                for (int g = 0; g < 4; g++)
                    w2[g] = *(ulonglong2*)&Ws0[(g * 16 + jl) * WPAD + k];
#pragma unroll
                for (int m = 0; m < 4; m++)
#pragma unroll
                    for (int g = 0; g < 4; g++) {
                        ffma2(acc0[m][g], h2[m].x, w2[g].x);
                        ffma2(acc0[m][g], h2[m].y, w2[g].y);
                    }
            }
        }

        // ================= layer 1: h1(u-2).W_hh1 + h0(u-1).W_ih1 ========
        ull acc1[4][4];
#pragma unroll
        for (int m = 0; m < 4; m++)
#pragma unroll
            for (int g = 0; g < 4; g++) acc1[m][g] = 0ull;

        if (u >= 1) {
            // kick off first two W_ih1 chunk loads (16 k each)
#pragma unroll
            for (int c0i = 0; c0i < 2; c0i++) {
#pragma unroll
                for (int i = 0; i < 2; i++) {
                    int lin = i * 128 + lt;
                    int row = lin >> 2;
                    int f4  = lin & 3;
                    int g   = row >> 4;
                    int jloc= row & 15;
                    const float* src = Wih1 + (size_t)(g * HH + jj + jloc) * HH
                                       + kb + c0i * 16 + f4 * 4;
                    uint32_t dst = cb_u32 +
                        (uint32_t)((c0i * 64 * CPAD + row * CPAD + f4 * 4) * 4);
                    cp_async16(dst, src);
                }
                asm volatile("cp.async.commit_group;" ::: "memory");
            }

            // hh GEMM (covers cp.async latency for first chunks)
#pragma unroll 4
            for (int k = kb; k < kb + 128; k += 4) {
                ulonglong2 h2[4], w2[4];
#pragma unroll
                for (int m = 0; m < 4; m++)
                    h2[m] = *(ulonglong2*)&Hs1[(br + 8 * m) * WPAD + k];
#pragma unroll
                for (int g = 0; g < 4; g++)
                    w2[g] = *(ulonglong2*)&Ws1[(g * 16 + jl) * WPAD + k];
#pragma unroll
                for (int m = 0; m < 4; m++)
#pragma unroll
                    for (int g = 0; g < 4; g++) {
                        ffma2(acc1[m][g], h2[m].x, w2[g].x);
                        ffma2(acc1[m][g], h2[m].y, w2[g].y);
                    }
            }

            // ih GEMM over 8 chunks, double-buffered
#pragma unroll
            for (int c = 0; c < 8; c++) {
                if (c == 7) asm volatile("cp.async.wait_group 0;" ::: "memory");
                else        asm volatile("cp.async.wait_group 1;" ::: "memory");
                asm volatile("bar.sync %0, 128;" :: "r"(kg + 1) : "memory");

                const float* cbuf = cb_kg + (c & 1) * 64 * CPAD;
#pragma unroll
                for (int kk = 0; kk < 16; kk += 4) {
                    int k = kb + c * 16 + kk;
                    ulonglong2 h2[4], w2[4];
#pragma unroll
                    for (int m = 0; m < 4; m++)
                        h2[m] = *(ulonglong2*)&Hs0[(br + 8 * m) * WPAD + k];
#pragma unroll
                    for (int g = 0; g < 4; g++)
                        w2[g] = *(ulonglong2*)&cbuf[(g * 16 + jl) * CPAD + kk];
#pragma unroll
                    for (int m = 0; m < 4; m++)
#pragma unroll
                        for (int g = 0; g < 4; g++) {
                            ffma2(acc1[m][g], h2[m].x, w2[g].x);
                            ffma2(acc1[m][g], h2[m].y, w2[g].y);
                        }
                }
                asm volatile("bar.sync %0, 128;" :: "r"(kg + 1) : "memory");

                if (c + 2 < 8) {
#pragma unroll
                    for (int i = 0; i < 2; i++) {
                        int lin = i * 128 + lt;
                        int row = lin >> 2;
                        int f4  = lin & 3;
                        int g   = row >> 4;
                        int jloc= row & 15;
                        const float* src = Wih1 + (size_t)(g * HH + jj + jloc) * HH
                                           + kb + (c + 2) * 16 + f4 * 4;
                        uint32_t dst = cb_u32 +
                            (uint32_t)(((c & 1) * 64 * CPAD + row * CPAD + f4 * 4) * 4);
                        cp_async16(dst, src);
                    }
                    asm volatile("cp.async.commit_group;" ::: "memory");
                }
            }
        }

        // ---- phase A: kg1 publishes layer-0 partials
        if (kg == 1 && u < TT) {
#pragma unroll
            for (int m = 0; m < 4; m++)
#pragma unroll
                for (int g = 0; g < 4; g++)
                    Rs[(8 * m + br) * RPAD + g * 16 + jl] = red2(acc0[m][g]);
        }
        __syncthreads();

        // ---- phase B: kg0 epilogue layer 0 -> h0(u)
        if (kg == 0 && u < TT) {
            float* hout = h0buf + (size_t)(u & 1) * BHH;
#pragma unroll
            for (int m = 0; m < 4; m++) {
                int b = bb + br + 8 * m;
                const float* rrow = &Rs[(8 * m + br) * RPAD];
                float vi = red2(acc0[m][0]) + rrow[0 * 16 + jl] + xv_cur[m][0];
                float vf = red2(acc0[m][1]) + rrow[1 * 16 + jl] + xv_cur[m][1];
                float vg = red2(acc0[m][2]) + rrow[2 * 16 + jl] + xv_cur[m][2];
                float vo = red2(acc0[m][3]) + rrow[3 * 16 + jl] + xv_cur[m][3];

                float ig = fsig(vi), fg = fsig(vf), gg = ftanh(vg), og = fsig(vo);
                float cn = fg * cacc0[m] + ig * gg;
                cacc0[m] = cn;
                __stcg(hout + (size_t)b * HH + j, og * ftanh(cn));
#pragma unroll
                for (int g = 0; g < 4; g++) xv_cur[m][g] = xv_nxt[m][g];
            }
        }
        __syncthreads();

        // ---- phase C: kg1 publishes layer-1 partials
        if (kg == 1 && u >= 1) {
#pragma unroll
            for (int m = 0; m < 4; m++)
#pragma unroll
                for (int g = 0; g < 4; g++)
                    Rs[(8 * m + br) * RPAD + g * 16 + jl] = red2(acc1[m][g]);
        }
        __syncthreads();

        // ---- phase D: kg0 epilogue layer 1 -> h1(u-1)
        if (kg == 0 && u >= 1) {
            float* hout = h1buf + (size_t)((u - 1) & 1) * BHH;
#pragma unroll
            for (int m = 0; m < 4; m++) {
                int b = bb + br + 8 * m;
                const float* rrow = &Rs[(8 * m + br) * RPAD];
                float vi = red2(acc1[m][0]) + rrow[0 * 16 + jl] + bias1[0];
                float vf = red2(acc1[m][1]) + rrow[1 * 16 + jl] + bias1[1];
                float vg = red2(acc1[m][2]) + rrow[2 * 16 + jl] + bias1[2];
                float vo = red2(acc1[m][3]) + rrow[3 * 16 + jl] + bias1[3];

                float ig = fsig(vi), fg = fsig(vf), gg = ftanh(vg), og = fsig(vo);
                float cn = fg * cacc1[m] + ig * gg;
                cacc1[m] = cn;
                float hn = og * ftanh(cn);
                __stcg(hout + (size_t)b * HH + j, hn);
                if (u == TT) hlast[(size_t)b * HH + j] = hn;
            }
        }

        // ---- arrive
        __syncthreads();
        if (tid == 0) {
            __threadfence();
            *(volatile unsigned*)&g_flag[(bt * GROUP_CTAS + jt) * 32] =
                (unsigned)(u + 1);
        }
    }
}

// ---------------- launcher ---------------------------------------------------
extern "C" void kernel_launch(void* const* d_in, const int* in_sizes, int n_in,
                              void* d_out, int out_size)
{
    const float* x     = (const float*)d_in[0];
    const float* W_ih0 = (const float*)d_in[1];
    const float* W_hh0 = (const float*)d_in[2];
    const float* b_ih0 = (const float*)d_in[3];
    const float* b_hh0 = (const float*)d_in[4];
    const float* W_ih1 = (const float*)d_in[5];
    const float* W_hh1 = (const float*)d_in[6];
    const float* b_ih1 = (const float*)d_in[7];
    const float* b_hh1 = (const float*)d_in[8];
    const float* W_fc  = (const float*)d_in[9];
    float* outp = (float*)d_out;
    (void)in_sizes; (void)n_in; (void)out_size;

    float *XP, *H0, *H1, *HLAST;
    cudaGetSymbolAddress((void**)&XP,    g_XP);
    cudaGetSymbolAddress((void**)&H0,    g_H0);
    cudaGetSymbolAddress((void**)&H1,    g_H1);
    cudaGetSymbolAddress((void**)&HLAST, g_HLAST);

    static bool attr_set = false;
    if (!attr_set) {
        cudaFuncSetAttribute(lstm_fused_kernel,
                             cudaFuncAttributeMaxDynamicSharedMemorySize,
                             FUSED_FLOATS * (int)sizeof(float));
        attr_set = true;
    }
    const size_t fsmemB = FUSED_FLOATS * sizeof(float);

    init_kernel<<<(2 * BHH + 255) / 256, 256>>>();
    gemm_bias_kernel<DIN><<<dim3(16, 4, TT), 256>>>(
        x, (size_t)TT * DIN, (size_t)DIN, W_ih0, b_ih0, b_hh0, XP, G4);
    lstm_fused_kernel<<<NB_CTAS, 256, fsmemB>>>(
        XP, W_hh0, W_hh1, W_ih1, b_ih1, b_hh1, H0, H1, HLAST);

    // ---------- final FC: out = h1_last @ W_fc^T ----------
    gemm_bias_kernel<HH><<<dim3(2, 4, 1), 256>>>(
        HLAST, (size_t)HH, 0, W_fc, nullptr, nullptr, outp, OUTF);
}